// round 2
// baseline (speedup 1.0000x reference)
#include <cuda_runtime.h>
#include <cuda_bf16.h>
#include <math.h>

// Problem constants
#define BB   16
#define LL   1024
#define DD   768
#define HH   4
#define CC   256
#define EE   8192
#define HC   1024           // H*C
#define EL   (EE + LL)      // 9216 edges incl. self loops
#define KOUT (DD + HC)      // 1792

// ---------------- scratch (device globals; no allocation allowed) -----------
__device__ __align__(16) float g_h  [(size_t)BB * LL * HC];   // [B*L, H*C]
__device__ __align__(16) float g_gat[(size_t)BB * LL * HC];   // aggregated GAT out
__device__ __align__(16) float g_as [BB * LL * HH];
__device__ __align__(16) float g_ad [BB * LL * HH];
__device__ __align__(16) float g_max[BB * LL * HH];
__device__ __align__(16) float g_den[BB * LL * HH];
__device__ __align__(16) float g_ebuf[BB * EL * HH];          // per-edge logits -> probs

// ---------------- helpers ----------------------------------------------------
__device__ __forceinline__ void redAdd4(float* p, float4 v) {
    asm volatile("red.global.add.v4.f32 [%0], {%1,%2,%3,%4};"
                 :: "l"(p), "f"(v.x), "f"(v.y), "f"(v.z), "f"(v.w) : "memory");
}

// ---------------- init: zero gat accumulator, init max/den -------------------
__global__ void init_kernel() {
    int i = blockIdx.x * blockDim.x + threadIdx.x;
    if (i < (BB * LL * HC) / 4)
        reinterpret_cast<float4*>(g_gat)[i] = make_float4(0.f, 0.f, 0.f, 0.f);
    if (i < BB * LL * HH) {
        g_max[i] = -INFINITY;
        g_den[i] = 0.f;
    }
}

// ---------------- tiled fp32 GEMM:  C[M,N] = A[M,K] * B[N,K]^T (+bias) -------
// SPLIT: A is virtual concat [x | gat + b_gat] with split at K1.
template<bool SPLIT>
__global__ void __launch_bounds__(256)
gemm_nt(const float* __restrict__ A, const float* __restrict__ A2,
        const float* __restrict__ add2,
        const float* __restrict__ Bm, const float* __restrict__ bias,
        float* __restrict__ C, int M, int N, int K, int K1)
{
    __shared__ float As[16][128];
    __shared__ float Bs[16][128];

    const int tid = threadIdx.x;
    const int bm  = blockIdx.y * 128;
    const int bn  = blockIdx.x * 128;
    const int tm  = (tid >> 4) << 3;    // 0..120
    const int tn  = (tid & 15) << 3;    // 0..120

    float acc[8][8];
#pragma unroll
    for (int i = 0; i < 8; i++)
#pragma unroll
        for (int j = 0; j < 8; j++) acc[i][j] = 0.f;

    for (int k0 = 0; k0 < K; k0 += 16) {
#pragma unroll
        for (int e = 0; e < 2; e++) {
            int fid = tid + e * 256;          // 0..511 (float4 id)
            int row = fid >> 2;               // 0..127
            int kk  = (fid & 3) << 2;         // 0,4,8,12
            int gk  = k0 + kk;
            float4 va;
            if (SPLIT) {
                if (gk < K1) {
                    va = *(const float4*)&A[(size_t)(bm + row) * K1 + gk];
                } else {
                    int g2 = gk - K1;
                    va = *(const float4*)&A2[(size_t)(bm + row) * (K - K1) + g2];
                    float4 bb = *(const float4*)&add2[g2];
                    va.x += bb.x; va.y += bb.y; va.z += bb.z; va.w += bb.w;
                }
            } else {
                va = *(const float4*)&A[(size_t)(bm + row) * K + gk];
            }
            As[kk + 0][row] = va.x; As[kk + 1][row] = va.y;
            As[kk + 2][row] = va.z; As[kk + 3][row] = va.w;

            float4 vb = *(const float4*)&Bm[(size_t)(bn + row) * K + gk];
            Bs[kk + 0][row] = vb.x; Bs[kk + 1][row] = vb.y;
            Bs[kk + 2][row] = vb.z; Bs[kk + 3][row] = vb.w;
        }
        __syncthreads();

#pragma unroll
        for (int kk = 0; kk < 16; kk++) {
            float4 a0 = *(const float4*)&As[kk][tm];
            float4 a1 = *(const float4*)&As[kk][tm + 4];
            float4 b0 = *(const float4*)&Bs[kk][tn];
            float4 b1 = *(const float4*)&Bs[kk][tn + 4];
            float ar[8] = {a0.x, a0.y, a0.z, a0.w, a1.x, a1.y, a1.z, a1.w};
            float br[8] = {b0.x, b0.y, b0.z, b0.w, b1.x, b1.y, b1.z, b1.w};
#pragma unroll
            for (int i = 0; i < 8; i++)
#pragma unroll
                for (int j = 0; j < 8; j++)
                    acc[i][j] = fmaf(ar[i], br[j], acc[i][j]);
        }
        __syncthreads();
    }

    float bb[8];
#pragma unroll
    for (int j = 0; j < 8; j++) bb[j] = bias ? bias[bn + tn + j] : 0.f;

#pragma unroll
    for (int i = 0; i < 8; i++) {
        size_t row = (size_t)(bm + tm + i);
        float4 o0 = make_float4(acc[i][0] + bb[0], acc[i][1] + bb[1],
                                acc[i][2] + bb[2], acc[i][3] + bb[3]);
        float4 o1 = make_float4(acc[i][4] + bb[4], acc[i][5] + bb[5],
                                acc[i][6] + bb[6], acc[i][7] + bb[7]);
        *(float4*)&C[row * N + bn + tn]     = o0;
        *(float4*)&C[row * N + bn + tn + 4] = o1;
    }
}

// ---------------- attention scores: a_s, a_d (one warp per (node, head)) -----
__global__ void attn_scores(const float* __restrict__ att_src,
                            const float* __restrict__ att_dst)
{
    int gtid = blockIdx.x * blockDim.x + threadIdx.x;
    int warp = gtid >> 5;
    int lane = gtid & 31;
    if (warp >= BB * LL * HH) return;
    int hh = warp & (HH - 1);
    size_t node = (size_t)(warp >> 2);            // b*L + n
    const float* hv = g_h + node * HC + hh * CC;
    float s = 0.f, d = 0.f;
#pragma unroll
    for (int c = lane; c < CC; c += 32) {
        float v = hv[c];
        s = fmaf(v, att_src[hh * CC + c], s);
        d = fmaf(v, att_dst[hh * CC + c], d);
    }
#pragma unroll
    for (int off = 16; off; off >>= 1) {
        s += __shfl_down_sync(0xffffffffu, s, off);
        d += __shfl_down_sync(0xffffffffu, d, off);
    }
    if (lane == 0) { g_as[warp] = s; g_ad[warp] = d; }
}

// ---------------- pass A: per-edge logit + segment max -----------------------
__global__ void edge_logits(const int* __restrict__ ei) {
    int idx = blockIdx.x * blockDim.x + threadIdx.x;
    if (idx >= BB * EL * HH) return;
    int hh = idx & (HH - 1);
    int t  = idx >> 2;
    int e  = t % EL;
    int b  = t / EL;
    int src, dst;
    if (e < EE) { src = ei[b * 2 * EE + e]; dst = ei[b * 2 * EE + EE + e]; }
    else        { src = dst = e - EE; }
    float v = g_as[(b * LL + src) * HH + hh] + g_ad[(b * LL + dst) * HH + hh];
    v = v > 0.f ? v : 0.2f * v;               // leaky_relu(0.2)
    g_ebuf[idx] = v;
    float* mp = &g_max[(b * LL + dst) * HH + hh];
    if (v >= 0.f) atomicMax((int*)mp, __float_as_int(v));
    else          atomicMin((unsigned int*)mp, (unsigned int)__float_as_int(v));
}

// ---------------- pass B: exp(e - max), segment sum --------------------------
__global__ void edge_softmax(const int* __restrict__ ei) {
    int idx = blockIdx.x * blockDim.x + threadIdx.x;
    if (idx >= BB * EL * HH) return;
    int hh = idx & (HH - 1);
    int t  = idx >> 2;
    int e  = t % EL;
    int b  = t / EL;
    int dst;
    if (e < EE) dst = ei[b * 2 * EE + EE + e];
    else        dst = e - EE;
    int db = (b * LL + dst) * HH + hh;
    float p = __expf(g_ebuf[idx] - g_max[db]);
    g_ebuf[idx] = p;
    atomicAdd(&g_den[db], p);
}

// ---------------- pass C: aggregate gat[dst] += alpha * h[src] ---------------
__global__ void aggregate(const int* __restrict__ ei) {
    int gtid = blockIdx.x * blockDim.x + threadIdx.x;
    int warp = gtid >> 5;
    int lane = gtid & 31;
    if (warp >= BB * EL) return;
    int b = warp / EL;
    int e = warp % EL;
    int src, dst;
    if (e < EE) { src = ei[b * 2 * EE + e]; dst = ei[b * 2 * EE + EE + e]; }
    else        { src = dst = e - EE; }
    const float* hsrc = g_h   + (size_t)(b * LL + src) * HC;
    float*       gdst = g_gat + (size_t)(b * LL + dst) * HC;
    int ebase = (b * EL + e) * HH;
    int dbase = (b * LL + dst) * HH;
#pragma unroll
    for (int hh = 0; hh < HH; hh++) {
        float alpha = g_ebuf[ebase + hh] / (g_den[dbase + hh] + 1e-16f);
        int c0 = hh * CC + lane * 8;
        float4 v0 = *(const float4*)&hsrc[c0];
        float4 v1 = *(const float4*)&hsrc[c0 + 4];
        v0.x *= alpha; v0.y *= alpha; v0.z *= alpha; v0.w *= alpha;
        v1.x *= alpha; v1.y *= alpha; v1.z *= alpha; v1.w *= alpha;
        redAdd4(&gdst[c0], v0);
        redAdd4(&gdst[c0 + 4], v1);
    }
}

// ---------------- launch ------------------------------------------------------
extern "C" void kernel_launch(void* const* d_in, const int* in_sizes, int n_in,
                              void* d_out, int out_size)
{
    const float* x    = (const float*)d_in[0];   // [B,L,D]
    const int*   ei   = (const int*)  d_in[1];   // [B,2,E]
    const float* Wg   = (const float*)d_in[2];   // [H*C, D]
    const float* asrc = (const float*)d_in[3];   // [H, C]
    const float* adst = (const float*)d_in[4];   // [H, C]
    const float* bg   = (const float*)d_in[5];   // [H*C]
    const float* Wo   = (const float*)d_in[6];   // [D, H*C+D]
    const float* bo   = (const float*)d_in[7];   // [D]
    float* out = (float*)d_out;

    float *p_h = nullptr, *p_gat = nullptr;
    cudaGetSymbolAddress((void**)&p_h,   g_h);
    cudaGetSymbolAddress((void**)&p_gat, g_gat);

    const int M = BB * LL;

    // 1) init scratch
    init_kernel<<<(M * HC / 4 + 255) / 256, 256>>>();

    // 2) h = x @ W_gat^T   [M,768]x[1024,768]^T -> [M,1024]
    gemm_nt<false><<<dim3(HC / 128, M / 128), 256>>>(
        x, nullptr, nullptr, Wg, nullptr, p_h, M, HC, DD, 0);

    // 3) a_s, a_d
    attn_scores<<<(BB * LL * HH * 32 + 255) / 256, 256>>>(asrc, adst);

    // 4) edge logits + segment max
    edge_logits<<<(BB * EL * HH + 255) / 256, 256>>>(ei);

    // 5) exp + segment sum
    edge_softmax<<<(BB * EL * HH + 255) / 256, 256>>>(ei);

    // 6) scatter-aggregate
    aggregate<<<(BB * EL * 32 + 255) / 256, 256>>>(ei);

    // 7) out = [x | gat + b_gat] @ W_out^T + b_out   [M,1792]x[768,1792]^T
    gemm_nt<true><<<dim3(DD / 128, M / 128), 256>>>(
        x, p_gat, bg, Wo, bo, out, M, DD, KOUT, DD);
}

// round 3
// speedup vs baseline: 2.8397x; 2.8397x over previous
#include <cuda_runtime.h>
#include <cuda_bf16.h>
#include <math.h>
#include <stdint.h>

// Problem constants
#define BB   16
#define LL   1024
#define DD   768
#define HH   4
#define CC   256
#define EE   8192
#define HC   1024           // H*C
#define EL   (EE + LL)      // 9216 edges incl. self loops
#define KOUT (DD + HC)      // 1792
#define MM   (BB * LL)      // 16384

// ---------------- scratch (device globals; no allocation allowed) -----------
__device__ __align__(16) float g_h   [(size_t)MM * HC];   // h = x @ Wg^T (fp32)
__device__ __align__(16) float g_gat [(size_t)MM * HC];   // aggregated GAT out (fp32)
__device__ __align__(16) float g_xr  [(size_t)MM * DD];   // tf32-rounded x
__device__ __align__(16) float g_gatr[(size_t)MM * HC];   // tf32-rounded (gat + b_gat)
__device__ __align__(16) float g_wgr [(size_t)HC * DD];   // tf32-rounded W_gat
__device__ __align__(16) float g_wor [(size_t)DD * KOUT]; // tf32-rounded W_out
__device__ __align__(16) float g_as  [MM * HH];
__device__ __align__(16) float g_ad  [MM * HH];
__device__ __align__(16) float g_max [MM * HH];
__device__ __align__(16) float g_den [MM * HH];
__device__ __align__(16) float g_ebuf[BB * EL * HH];      // per-edge logits -> probs

// ---------------- helpers ----------------------------------------------------
__device__ __forceinline__ void redAdd4(float* p, float4 v) {
    asm volatile("red.global.add.v4.f32 [%0], {%1,%2,%3,%4};"
                 :: "l"(p), "f"(v.x), "f"(v.y), "f"(v.z), "f"(v.w) : "memory");
}
__device__ __forceinline__ float tf32r(float x) {
    uint32_t u;
    asm("cvt.rna.tf32.f32 %0, %1;" : "=r"(u) : "f"(x));
    return __uint_as_float(u);
}
__device__ __forceinline__ void cp16(void* s, const void* g) {
    uint32_t sa = (uint32_t)__cvta_generic_to_shared(s);
    asm volatile("cp.async.cg.shared.global [%0], [%1], 16;" :: "r"(sa), "l"(g));
}
__device__ __forceinline__ void mma8(float* d, const uint32_t* a, const uint32_t* b) {
    asm volatile(
        "mma.sync.aligned.m16n8k8.row.col.f32.tf32.tf32.f32 "
        "{%0,%1,%2,%3}, {%4,%5,%6,%7}, {%8,%9}, {%0,%1,%2,%3};"
        : "+f"(d[0]), "+f"(d[1]), "+f"(d[2]), "+f"(d[3])
        : "r"(a[0]), "r"(a[1]), "r"(a[2]), "r"(a[3]), "r"(b[0]), "r"(b[1]));
}

// ---------------- init: zero gat accumulator, init max/den -------------------
__global__ void init_kernel() {
    int i = blockIdx.x * blockDim.x + threadIdx.x;
    if (i < (MM * HC) / 4)
        reinterpret_cast<float4*>(g_gat)[i] = make_float4(0.f, 0.f, 0.f, 0.f);
    if (i < MM * HH) {
        g_max[i] = -INFINITY;
        g_den[i] = 0.f;
    }
}

// ---------------- elementwise tf32 rounding ----------------------------------
__global__ void round_tf32_k(const float* __restrict__ in, float* __restrict__ out, int n4) {
    int i = blockIdx.x * blockDim.x + threadIdx.x;
    if (i >= n4) return;
    float4 v = reinterpret_cast<const float4*>(in)[i];
    v.x = tf32r(v.x); v.y = tf32r(v.y); v.z = tf32r(v.z); v.w = tf32r(v.w);
    reinterpret_cast<float4*>(out)[i] = v;
}

// gat + b_gat -> rounded
__global__ void round_gat_k(const float* __restrict__ bg) {
    int i = blockIdx.x * blockDim.x + threadIdx.x;
    if (i >= (MM * HC) / 4) return;
    float4 v = reinterpret_cast<const float4*>(g_gat)[i];
    float4 b = reinterpret_cast<const float4*>(bg)[i & (HC / 4 - 1)];
    v.x = tf32r(v.x + b.x); v.y = tf32r(v.y + b.y);
    v.z = tf32r(v.z + b.z); v.w = tf32r(v.w + b.w);
    reinterpret_cast<float4*>(g_gatr)[i] = v;
}

// ---------------- tf32 tensor-core GEMM: C[M,N] = A[M,K] * B[N,K]^T (+bias) --
// 128x128x32 block tile, 8 warps, warp tile 64x32, mma m16n8k8.
// SPLIT: A is virtual concat [A (K1 cols) | A2 (K-K1 cols)], per-32 chunk.
#define LDT 36
#define TILE (128 * LDT)

template<bool SPLIT>
__global__ void __launch_bounds__(256)
gemm_tf32(const float* __restrict__ A, const float* __restrict__ A2,
          const float* __restrict__ Bm, const float* __restrict__ bias,
          float* __restrict__ C, int M, int N, int K, int K1)
{
    extern __shared__ float sm[];
    float* smA = sm;              // 2 stages of 128x36
    float* smB = sm + 2 * TILE;   // 2 stages of 128x36

    const int tid  = threadIdx.x;
    const int bm   = blockIdx.y * 128;
    const int bn   = blockIdx.x * 128;
    const int lane = tid & 31;
    const int warp = tid >> 5;
    const int wm   = warp & 1;        // 2 warps along M
    const int wn   = warp >> 1;       // 4 warps along N
    const int lr   = lane >> 2;
    const int lc   = lane & 3;

    float acc[4][4][4];
#pragma unroll
    for (int i = 0; i < 4; i++)
#pragma unroll
        for (int j = 0; j < 4; j++)
#pragma unroll
            for (int r = 0; r < 4; r++) acc[i][j][r] = 0.f;

    const int nk = K >> 5;

    auto load_tiles = [&](int st, int kt) {
        int k0 = kt << 5;
        const float* Ap; int lda, kc;
        if (!SPLIT || k0 < K1) { Ap = A;  lda = SPLIT ? K1 : K; kc = k0; }
        else                   { Ap = A2; lda = K - K1;         kc = k0 - K1; }
        float* sA = smA + st * TILE;
        float* sB = smB + st * TILE;
#pragma unroll
        for (int t = 0; t < 4; t++) {
            int fid = tid + t * 256;
            int row = fid >> 3;
            int kq  = (fid & 7) << 2;
            cp16(&sA[row * LDT + kq], &Ap[(size_t)(bm + row) * lda + kc + kq]);
            cp16(&sB[row * LDT + kq], &Bm[(size_t)(bn + row) * K + k0 + kq]);
        }
    };

    auto compute = [&](int st) {
        const float* sA = smA + st * TILE + (wm * 64 + lr) * LDT + lc;
        const float* sB = smB + st * TILE + (wn * 32 + lr) * LDT + lc;
#pragma unroll
        for (int ks = 0; ks < 32; ks += 8) {
            uint32_t af[4][4], bf[4][2];
#pragma unroll
            for (int i = 0; i < 4; i++) {
                const float* p = sA + i * 16 * LDT + ks;
                af[i][0] = __float_as_uint(p[0]);
                af[i][1] = __float_as_uint(p[8 * LDT]);
                af[i][2] = __float_as_uint(p[4]);
                af[i][3] = __float_as_uint(p[8 * LDT + 4]);
            }
#pragma unroll
            for (int j = 0; j < 4; j++) {
                const float* p = sB + j * 8 * LDT + ks;
                bf[j][0] = __float_as_uint(p[0]);
                bf[j][1] = __float_as_uint(p[4]);
            }
#pragma unroll
            for (int i = 0; i < 4; i++)
#pragma unroll
                for (int j = 0; j < 4; j++)
                    mma8(acc[i][j], af[i], bf[j]);
        }
    };

    load_tiles(0, 0);
    asm volatile("cp.async.commit_group;");
    for (int it = 0; it < nk; ++it) {
        if (it + 1 < nk) {
            load_tiles((it + 1) & 1, it + 1);
            asm volatile("cp.async.commit_group;");
            asm volatile("cp.async.wait_group 1;");
        } else {
            asm volatile("cp.async.wait_group 0;");
        }
        __syncthreads();
        compute(it & 1);
        __syncthreads();
    }

    // epilogue
#pragma unroll
    for (int j = 0; j < 4; j++) {
        int col = bn + wn * 32 + j * 8 + lc * 2;
        float b0 = bias ? bias[col] : 0.f;
        float b1 = bias ? bias[col + 1] : 0.f;
#pragma unroll
        for (int i = 0; i < 4; i++) {
            int row0 = bm + wm * 64 + i * 16 + lr;
            float2 v0 = make_float2(acc[i][j][0] + b0, acc[i][j][1] + b1);
            float2 v1 = make_float2(acc[i][j][2] + b0, acc[i][j][3] + b1);
            *(float2*)&C[(size_t)row0 * N + col]       = v0;
            *(float2*)&C[(size_t)(row0 + 8) * N + col] = v1;
        }
    }
}

// ---------------- attention scores: a_s, a_d (one warp per (node, head)) -----
__global__ void attn_scores(const float* __restrict__ att_src,
                            const float* __restrict__ att_dst)
{
    int gtid = blockIdx.x * blockDim.x + threadIdx.x;
    int warp = gtid >> 5;
    int lane = gtid & 31;
    if (warp >= MM * HH) return;
    int hh = warp & (HH - 1);
    size_t node = (size_t)(warp >> 2);
    const float* hv = g_h + node * HC + hh * CC;
    float s = 0.f, d = 0.f;
#pragma unroll
    for (int c = lane; c < CC; c += 32) {
        float v = hv[c];
        s = fmaf(v, att_src[hh * CC + c], s);
        d = fmaf(v, att_dst[hh * CC + c], d);
    }
#pragma unroll
    for (int off = 16; off; off >>= 1) {
        s += __shfl_down_sync(0xffffffffu, s, off);
        d += __shfl_down_sync(0xffffffffu, d, off);
    }
    if (lane == 0) { g_as[warp] = s; g_ad[warp] = d; }
}

// ---------------- pass A: per-edge logit + segment max -----------------------
__global__ void edge_logits(const int* __restrict__ ei) {
    int idx = blockIdx.x * blockDim.x + threadIdx.x;
    if (idx >= BB * EL * HH) return;
    int hh = idx & (HH - 1);
    int t  = idx >> 2;
    int e  = t % EL;
    int b  = t / EL;
    int src, dst;
    if (e < EE) { src = ei[b * 2 * EE + e]; dst = ei[b * 2 * EE + EE + e]; }
    else        { src = dst = e - EE; }
    float v = g_as[(b * LL + src) * HH + hh] + g_ad[(b * LL + dst) * HH + hh];
    v = v > 0.f ? v : 0.2f * v;
    g_ebuf[idx] = v;
    float* mp = &g_max[(b * LL + dst) * HH + hh];
    if (v >= 0.f) atomicMax((int*)mp, __float_as_int(v));
    else          atomicMin((unsigned int*)mp, (unsigned int)__float_as_int(v));
}

// ---------------- pass B: exp(e - max), segment sum --------------------------
__global__ void edge_softmax(const int* __restrict__ ei) {
    int idx = blockIdx.x * blockDim.x + threadIdx.x;
    if (idx >= BB * EL * HH) return;
    int hh = idx & (HH - 1);
    int t  = idx >> 2;
    int e  = t % EL;
    int b  = t / EL;
    int dst;
    if (e < EE) dst = ei[b * 2 * EE + EE + e];
    else        dst = e - EE;
    int db = (b * LL + dst) * HH + hh;
    float p = __expf(g_ebuf[idx] - g_max[db]);
    g_ebuf[idx] = p;
    atomicAdd(&g_den[db], p);
}

// ---------------- pass C: aggregate gat[dst] += alpha * h[src] ---------------
__global__ void aggregate(const int* __restrict__ ei) {
    int gtid = blockIdx.x * blockDim.x + threadIdx.x;
    int warp = gtid >> 5;
    int lane = gtid & 31;
    if (warp >= BB * EL) return;
    int b = warp / EL;
    int e = warp % EL;
    int src, dst;
    if (e < EE) { src = ei[b * 2 * EE + e]; dst = ei[b * 2 * EE + EE + e]; }
    else        { src = dst = e - EE; }
    const float* hsrc = g_h   + (size_t)(b * LL + src) * HC;
    float*       gdst = g_gat + (size_t)(b * LL + dst) * HC;
    int ebase = (b * EL + e) * HH;
    int dbase = (b * LL + dst) * HH;
#pragma unroll
    for (int hh = 0; hh < HH; hh++) {
        float alpha = g_ebuf[ebase + hh] / (g_den[dbase + hh] + 1e-16f);
        int c0 = hh * CC + lane * 8;
        float4 v0 = *(const float4*)&hsrc[c0];
        float4 v1 = *(const float4*)&hsrc[c0 + 4];
        v0.x *= alpha; v0.y *= alpha; v0.z *= alpha; v0.w *= alpha;
        v1.x *= alpha; v1.y *= alpha; v1.z *= alpha; v1.w *= alpha;
        redAdd4(&gdst[c0], v0);
        redAdd4(&gdst[c0 + 4], v1);
    }
}

// ---------------- launch ------------------------------------------------------
extern "C" void kernel_launch(void* const* d_in, const int* in_sizes, int n_in,
                              void* d_out, int out_size)
{
    const float* x    = (const float*)d_in[0];   // [B,L,D]
    const int*   ei   = (const int*)  d_in[1];   // [B,2,E]
    const float* Wg   = (const float*)d_in[2];   // [H*C, D]
    const float* asrc = (const float*)d_in[3];   // [H, C]
    const float* adst = (const float*)d_in[4];   // [H, C]
    const float* bg   = (const float*)d_in[5];   // [H*C]
    const float* Wo   = (const float*)d_in[6];   // [D, H*C+D]
    const float* bo   = (const float*)d_in[7];   // [D]
    float* out = (float*)d_out;

    float *p_h, *p_xr, *p_gatr, *p_wgr, *p_wor;
    cudaGetSymbolAddress((void**)&p_h,    g_h);
    cudaGetSymbolAddress((void**)&p_xr,   g_xr);
    cudaGetSymbolAddress((void**)&p_gatr, g_gatr);
    cudaGetSymbolAddress((void**)&p_wgr,  g_wgr);
    cudaGetSymbolAddress((void**)&p_wor,  g_wor);

    const int smem_bytes = 4 * TILE * sizeof(float);  // 73728
    cudaFuncSetAttribute(gemm_tf32<false>, cudaFuncAttributeMaxDynamicSharedMemorySize, smem_bytes);
    cudaFuncSetAttribute(gemm_tf32<true>,  cudaFuncAttributeMaxDynamicSharedMemorySize, smem_bytes);

    // 1) init scratch
    init_kernel<<<(MM * HC / 4 + 255) / 256, 256>>>();

    // 2) tf32-round GEMM inputs
    round_tf32_k<<<(MM * DD / 4 + 255) / 256, 256>>>(x,  p_xr,  MM * DD / 4);
    round_tf32_k<<<(HC * DD / 4 + 255) / 256, 256>>>(Wg, p_wgr, HC * DD / 4);
    round_tf32_k<<<(DD * KOUT / 4 + 255) / 256, 256>>>(Wo, p_wor, DD * KOUT / 4);

    // 3) h = x @ W_gat^T   [M,768]x[1024,768]^T -> [M,1024]
    gemm_tf32<false><<<dim3(HC / 128, MM / 128), 256, smem_bytes>>>(
        p_xr, nullptr, p_wgr, nullptr, p_h, MM, HC, DD, 0);

    // 4) a_s, a_d
    attn_scores<<<(MM * HH * 32 + 255) / 256, 256>>>(asrc, adst);

    // 5) edge logits + segment max
    edge_logits<<<(BB * EL * HH + 255) / 256, 256>>>(ei);

    // 6) exp + segment sum
    edge_softmax<<<(BB * EL * HH + 255) / 256, 256>>>(ei);

    // 7) scatter-aggregate
    aggregate<<<(BB * EL * 32 + 255) / 256, 256>>>(ei);

    // 8) round (gat + b_gat)
    round_gat_k<<<(MM * HC / 4 + 255) / 256, 256>>>(bg);

    // 9) out = [x | gat + b_gat] @ W_out^T + b_out   [M,1792]x[768,1792]^T
    gemm_tf32<true><<<dim3(DD / 128, MM / 128), 256, smem_bytes>>>(
        p_xr, p_gatr, p_wor, bo, out, MM, DD, KOUT, DD);
}

// round 4
// speedup vs baseline: 3.4031x; 1.1984x over previous
#include <cuda_runtime.h>
#include <cuda_bf16.h>
#include <math.h>
#include <stdint.h>

// Problem constants
#define BB   16
#define LL   1024
#define DD   768
#define HH   4
#define CC   256
#define EE   8192
#define HC   1024           // H*C
#define EL   (EE + LL)      // 9216 edges incl. self loops
#define KOUT (DD + HC)      // 1792
#define MM   (BB * LL)      // 16384

// ---------------- scratch (device globals; no allocation allowed) -----------
__device__ __align__(16) float g_h   [(size_t)MM * HC];   // h = x @ Wg^T (fp32)
__device__ __align__(16) float g_xr  [(size_t)MM * DD];   // tf32-rounded x
__device__ __align__(16) float g_gatr[(size_t)MM * HC];   // tf32-rounded (gat + b_gat)
__device__ __align__(16) float g_wgr [(size_t)HC * DD];   // tf32-rounded W_gat
__device__ __align__(16) float g_wor [(size_t)DD * KOUT]; // tf32-rounded W_out
__device__ __align__(16) float g_as  [MM * HH];
__device__ __align__(16) float g_ad  [MM * HH];
__device__ __align__(16) float g_max [MM * HH];
__device__ __align__(16) float g_den [MM * HH];
__device__ __align__(16) float g_ebuf[BB * EL * HH];      // per-edge probs
__device__ int g_deg[MM];          // in-degree per node
__device__ int g_off[MM + 1];      // CSR offsets
__device__ int g_cur[MM];          // scatter cursors
__device__ int g_csr[BB * EL];     // packed (eid<<10 | src)

// ---------------- helpers ----------------------------------------------------
__device__ __forceinline__ float tf32r(float x) {
    uint32_t u;
    asm("cvt.rna.tf32.f32 %0, %1;" : "=r"(u) : "f"(x));
    return __uint_as_float(u);
}
__device__ __forceinline__ void cp16(void* s, const void* g) {
    uint32_t sa = (uint32_t)__cvta_generic_to_shared(s);
    asm volatile("cp.async.cg.shared.global [%0], [%1], 16;" :: "r"(sa), "l"(g));
}
__device__ __forceinline__ void mma8(float* d, const uint32_t* a, const uint32_t* b) {
    asm volatile(
        "mma.sync.aligned.m16n8k8.row.col.f32.tf32.tf32.f32 "
        "{%0,%1,%2,%3}, {%4,%5,%6,%7}, {%8,%9}, {%0,%1,%2,%3};"
        : "+f"(d[0]), "+f"(d[1]), "+f"(d[2]), "+f"(d[3])
        : "r"(a[0]), "r"(a[1]), "r"(a[2]), "r"(a[3]), "r"(b[0]), "r"(b[1]));
}

// ---------------- init: degrees, max, den ------------------------------------
__global__ void init_kernel() {
    int i = blockIdx.x * blockDim.x + threadIdx.x;
    if (i < MM * HH) {
        g_max[i] = -INFINITY;
        g_den[i] = 0.f;
    }
    if (i < MM) g_deg[i] = 0;
}

// ---------------- elementwise tf32 rounding ----------------------------------
__global__ void round_tf32_k(const float* __restrict__ in, float* __restrict__ out, int n4) {
    int i = blockIdx.x * blockDim.x + threadIdx.x;
    if (i >= n4) return;
    float4 v = reinterpret_cast<const float4*>(in)[i];
    v.x = tf32r(v.x); v.y = tf32r(v.y); v.z = tf32r(v.z); v.w = tf32r(v.w);
    reinterpret_cast<float4*>(out)[i] = v;
}

// ---------------- tf32 tensor-core GEMM (same as R2, proven) -----------------
#define LDT 36
#define TILE (128 * LDT)

template<bool SPLIT>
__global__ void __launch_bounds__(256)
gemm_tf32(const float* __restrict__ A, const float* __restrict__ A2,
          const float* __restrict__ Bm, const float* __restrict__ bias,
          float* __restrict__ C, int M, int N, int K, int K1)
{
    extern __shared__ float sm[];
    float* smA = sm;
    float* smB = sm + 2 * TILE;

    const int tid  = threadIdx.x;
    const int bm   = blockIdx.y * 128;
    const int bn   = blockIdx.x * 128;
    const int lane = tid & 31;
    const int warp = tid >> 5;
    const int wm   = warp & 1;
    const int wn   = warp >> 1;
    const int lr   = lane >> 2;
    const int lc   = lane & 3;

    float acc[4][4][4];
#pragma unroll
    for (int i = 0; i < 4; i++)
#pragma unroll
        for (int j = 0; j < 4; j++)
#pragma unroll
            for (int r = 0; r < 4; r++) acc[i][j][r] = 0.f;

    const int nk = K >> 5;

    auto load_tiles = [&](int st, int kt) {
        int k0 = kt << 5;
        const float* Ap; int lda, kc;
        if (!SPLIT || k0 < K1) { Ap = A;  lda = SPLIT ? K1 : K; kc = k0; }
        else                   { Ap = A2; lda = K - K1;         kc = k0 - K1; }
        float* sA = smA + st * TILE;
        float* sB = smB + st * TILE;
#pragma unroll
        for (int t = 0; t < 4; t++) {
            int fid = tid + t * 256;
            int row = fid >> 3;
            int kq  = (fid & 7) << 2;
            cp16(&sA[row * LDT + kq], &Ap[(size_t)(bm + row) * lda + kc + kq]);
            cp16(&sB[row * LDT + kq], &Bm[(size_t)(bn + row) * K + k0 + kq]);
        }
    };

    auto compute = [&](int st) {
        const float* sA = smA + st * TILE + (wm * 64 + lr) * LDT + lc;
        const float* sB = smB + st * TILE + (wn * 32 + lr) * LDT + lc;
#pragma unroll
        for (int ks = 0; ks < 32; ks += 8) {
            uint32_t af[4][4], bf[4][2];
#pragma unroll
            for (int i = 0; i < 4; i++) {
                const float* p = sA + i * 16 * LDT + ks;
                af[i][0] = __float_as_uint(p[0]);
                af[i][1] = __float_as_uint(p[8 * LDT]);
                af[i][2] = __float_as_uint(p[4]);
                af[i][3] = __float_as_uint(p[8 * LDT + 4]);
            }
#pragma unroll
            for (int j = 0; j < 4; j++) {
                const float* p = sB + j * 8 * LDT + ks;
                bf[j][0] = __float_as_uint(p[0]);
                bf[j][1] = __float_as_uint(p[4]);
            }
#pragma unroll
            for (int i = 0; i < 4; i++)
#pragma unroll
                for (int j = 0; j < 4; j++)
                    mma8(acc[i][j], af[i], bf[j]);
        }
    };

    load_tiles(0, 0);
    asm volatile("cp.async.commit_group;");
    for (int it = 0; it < nk; ++it) {
        if (it + 1 < nk) {
            load_tiles((it + 1) & 1, it + 1);
            asm volatile("cp.async.commit_group;");
            asm volatile("cp.async.wait_group 1;");
        } else {
            asm volatile("cp.async.wait_group 0;");
        }
        __syncthreads();
        compute(it & 1);
        __syncthreads();
    }

#pragma unroll
    for (int j = 0; j < 4; j++) {
        int col = bn + wn * 32 + j * 8 + lc * 2;
        float b0 = bias ? bias[col] : 0.f;
        float b1 = bias ? bias[col + 1] : 0.f;
#pragma unroll
        for (int i = 0; i < 4; i++) {
            int row0 = bm + wm * 64 + i * 16 + lr;
            float2 v0 = make_float2(acc[i][j][0] + b0, acc[i][j][1] + b1);
            float2 v1 = make_float2(acc[i][j][2] + b0, acc[i][j][3] + b1);
            *(float2*)&C[(size_t)row0 * N + col]       = v0;
            *(float2*)&C[(size_t)(row0 + 8) * N + col] = v1;
        }
    }
}

// ---------------- attention scores: a_s, a_d ---------------------------------
__global__ void attn_scores(const float* __restrict__ att_src,
                            const float* __restrict__ att_dst)
{
    int gtid = blockIdx.x * blockDim.x + threadIdx.x;
    int warp = gtid >> 5;
    int lane = gtid & 31;
    if (warp >= MM * HH) return;
    int hh = warp & (HH - 1);
    size_t node = (size_t)(warp >> 2);
    const float* hv = g_h + node * HC + hh * CC;
    float s = 0.f, d = 0.f;
#pragma unroll
    for (int c = lane; c < CC; c += 32) {
        float v = hv[c];
        s = fmaf(v, att_src[hh * CC + c], s);
        d = fmaf(v, att_dst[hh * CC + c], d);
    }
#pragma unroll
    for (int off = 16; off; off >>= 1) {
        s += __shfl_down_sync(0xffffffffu, s, off);
        d += __shfl_down_sync(0xffffffffu, d, off);
    }
    if (lane == 0) { g_as[warp] = s; g_ad[warp] = d; }
}

// ---------------- pass A: per-edge logit + segment max + degree count --------
__global__ void edge_logits(const int* __restrict__ ei) {
    int idx = blockIdx.x * blockDim.x + threadIdx.x;
    if (idx >= BB * EL * HH) return;
    int hh = idx & (HH - 1);
    int t  = idx >> 2;
    int e  = t % EL;
    int b  = t / EL;
    int src, dst;
    if (e < EE) { src = ei[b * 2 * EE + e]; dst = ei[b * 2 * EE + EE + e]; }
    else        { src = dst = e - EE; }
    if (hh == 0) atomicAdd(&g_deg[b * LL + dst], 1);
    float v = g_as[(b * LL + src) * HH + hh] + g_ad[(b * LL + dst) * HH + hh];
    v = v > 0.f ? v : 0.2f * v;
    g_ebuf[idx] = v;
    float* mp = &g_max[(b * LL + dst) * HH + hh];
    if (v >= 0.f) atomicMax((int*)mp, __float_as_int(v));
    else          atomicMin((unsigned int*)mp, (unsigned int)__float_as_int(v));
}

// ---------------- scan: exclusive prefix sum over 16384 degrees --------------
__global__ void __launch_bounds__(1024) scan_k() {
    __shared__ int sp[1024];
    int tid = threadIdx.x;
    int base = tid * 16;
    int loc[16];
    int s = 0;
#pragma unroll
    for (int i = 0; i < 16; i++) { loc[i] = s; s += g_deg[base + i]; }
    sp[tid] = s;
    __syncthreads();
    for (int off = 1; off < 1024; off <<= 1) {
        int v = (tid >= off) ? sp[tid - off] : 0;
        __syncthreads();
        sp[tid] += v;
        __syncthreads();
    }
    int excl = sp[tid] - s;
#pragma unroll
    for (int i = 0; i < 16; i++) {
        g_off[base + i] = excl + loc[i];
        g_cur[base + i] = excl + loc[i];
    }
    if (tid == 1023) g_off[MM] = sp[1023];
}

// ---------------- scatter: fill CSR buckets ----------------------------------
__global__ void scatter_k(const int* __restrict__ ei) {
    int t = blockIdx.x * blockDim.x + threadIdx.x;
    if (t >= BB * EL) return;
    int e = t % EL;
    int b = t / EL;
    int src, dst;
    if (e < EE) { src = ei[b * 2 * EE + e]; dst = ei[b * 2 * EE + EE + e]; }
    else        { src = dst = e - EE; }
    int pos = atomicAdd(&g_cur[b * LL + dst], 1);
    g_csr[pos] = src | (e << 10);
}

// ---------------- pass B: exp(e - max), segment sum --------------------------
__global__ void edge_softmax(const int* __restrict__ ei) {
    int idx = blockIdx.x * blockDim.x + threadIdx.x;
    if (idx >= BB * EL * HH) return;
    int hh = idx & (HH - 1);
    int t  = idx >> 2;
    int e  = t % EL;
    int b  = t / EL;
    int dst;
    if (e < EE) dst = ei[b * 2 * EE + EE + e];
    else        dst = e - EE;
    int db = (b * LL + dst) * HH + hh;
    float p = __expf(g_ebuf[idx] - g_max[db]);
    g_ebuf[idx] = p;
    atomicAdd(&g_den[db], p);
}

// ---------------- gather: gat[node] = sum alpha*h[src], +bg, tf32-round ------
__global__ void __launch_bounds__(256) gather_k(const float* __restrict__ bg) {
    int node = blockIdx.x;         // 0..MM-1
    int b    = node >> 10;
    int tid  = threadIdx.x;
    int c    = tid << 2;           // channel base, 0..1020
    int head = c >> 8;             // 0..3

    float rden = 1.f / (g_den[node * HH + head] + 1e-16f);
    int start = g_off[node], end = g_off[node + 1];
    const float* hbase = g_h    + (size_t)(b << 10) * HC;
    const float* pbase = g_ebuf + (size_t)b * EL * HH;

    float4 acc = make_float4(0.f, 0.f, 0.f, 0.f);
    for (int i = start; i < end; i++) {
        int v   = g_csr[i];
        int src = v & 1023;
        int eid = v >> 10;
        float alpha = pbase[eid * HH + head] * rden;
        float4 hv = *(const float4*)(hbase + (size_t)src * HC + c);
        acc.x = fmaf(alpha, hv.x, acc.x);
        acc.y = fmaf(alpha, hv.y, acc.y);
        acc.z = fmaf(alpha, hv.z, acc.z);
        acc.w = fmaf(alpha, hv.w, acc.w);
    }
    float4 bb = *(const float4*)&bg[c];
    acc.x = tf32r(acc.x + bb.x); acc.y = tf32r(acc.y + bb.y);
    acc.z = tf32r(acc.z + bb.z); acc.w = tf32r(acc.w + bb.w);
    *(float4*)&g_gatr[(size_t)node * HC + c] = acc;
}

// ---------------- launch ------------------------------------------------------
extern "C" void kernel_launch(void* const* d_in, const int* in_sizes, int n_in,
                              void* d_out, int out_size)
{
    const float* x    = (const float*)d_in[0];
    const int*   ei   = (const int*)  d_in[1];
    const float* Wg   = (const float*)d_in[2];
    const float* asrc = (const float*)d_in[3];
    const float* adst = (const float*)d_in[4];
    const float* bg   = (const float*)d_in[5];
    const float* Wo   = (const float*)d_in[6];
    const float* bo   = (const float*)d_in[7];
    float* out = (float*)d_out;

    float *p_h, *p_xr, *p_gatr, *p_wgr, *p_wor;
    cudaGetSymbolAddress((void**)&p_h,    g_h);
    cudaGetSymbolAddress((void**)&p_xr,   g_xr);
    cudaGetSymbolAddress((void**)&p_gatr, g_gatr);
    cudaGetSymbolAddress((void**)&p_wgr,  g_wgr);
    cudaGetSymbolAddress((void**)&p_wor,  g_wor);

    const int smem_bytes = 4 * TILE * sizeof(float);
    cudaFuncSetAttribute(gemm_tf32<false>, cudaFuncAttributeMaxDynamicSharedMemorySize, smem_bytes);
    cudaFuncSetAttribute(gemm_tf32<true>,  cudaFuncAttributeMaxDynamicSharedMemorySize, smem_bytes);

    // 1) init
    init_kernel<<<(MM * HH + 255) / 256, 256>>>();

    // 2) tf32-round GEMM inputs
    round_tf32_k<<<(MM * DD / 4 + 255) / 256, 256>>>(x,  p_xr,  MM * DD / 4);
    round_tf32_k<<<(HC * DD / 4 + 255) / 256, 256>>>(Wg, p_wgr, HC * DD / 4);
    round_tf32_k<<<(DD * KOUT / 4 + 255) / 256, 256>>>(Wo, p_wor, DD * KOUT / 4);

    // 3) h = x @ W_gat^T
    gemm_tf32<false><<<dim3(HC / 128, MM / 128), 256, smem_bytes>>>(
        p_xr, nullptr, p_wgr, nullptr, p_h, MM, HC, DD, 0);

    // 4) a_s, a_d
    attn_scores<<<(MM * HH * 32 + 255) / 256, 256>>>(asrc, adst);

    // 5) logits + segment max + degree count
    edge_logits<<<(BB * EL * HH + 255) / 256, 256>>>(ei);

    // 6) CSR build
    scan_k<<<1, 1024>>>();
    scatter_k<<<(BB * EL + 255) / 256, 256>>>(ei);

    // 7) exp + segment sum
    edge_softmax<<<(BB * EL * HH + 255) / 256, 256>>>(ei);

    // 8) gather aggregate (+bias, tf32 round)
    gather_k<<<MM, 256>>>(bg);

    // 9) out = [x | gat] @ W_out^T + b_out
    gemm_tf32<true><<<dim3(DD / 128, MM / 128), 256, smem_bytes>>>(
        p_xr, p_gatr, p_wor, bo, out, MM, DD, KOUT, DD);
}